// round 16
// baseline (speedup 1.0000x reference)
#include <cuda_runtime.h>
#include <cuda_bf16.h>
#include <cstdint>

#define TOK 512
#define HID 2048
#define NE  64
#define NI  768
#define TOPK 8
#define CAP 256

#define ROWB   80u                 // smem row stride bytes (32 bf16 + 16B pad)
#define T_B    (128u * ROWB)       // 10240 : one 128-row tile
#define O_AHI  0u
#define O_ALO  T_B
#define O_BHI  (2u * T_B)
#define O_BLO  (3u * T_B)
#define STAGE  (4u * T_B)          // 40960 B
#define SMEM_BYTES (2 * STAGE)     // 81920 B

// ---------------- scratch (static device allocations) ----------------------
__device__ int   g_counts[NE];
__device__ int   g_sel[TOK * TOPK];
__device__ float g_rw[TOK * TOPK];
__device__ int   g_toklist[NE * CAP];
__device__ float g_slotw[NE * CAP];
__device__ unsigned short g_xhi[(size_t)TOK * HID];
__device__ unsigned short g_xlo[(size_t)TOK * HID];
__device__ unsigned short g_hhi[(size_t)NE * CAP * NI];
__device__ unsigned short g_hlo[(size_t)NE * CAP * NI];

// ---------------- helpers ---------------------------------------------------
__device__ __forceinline__ uint32_t smem_u32(const void* p) {
    uint32_t a;
    asm("{ .reg .u64 t; cvta.to.shared.u64 t, %1; cvt.u32.u64 %0, t; }"
        : "=r"(a) : "l"(p));
    return a;
}
__device__ __forceinline__ void ldsm4(uint32_t* r, uint32_t addr) {
    asm volatile("ldmatrix.sync.aligned.m8n8.x4.shared.b16 {%0,%1,%2,%3}, [%4];"
                 : "=r"(r[0]), "=r"(r[1]), "=r"(r[2]), "=r"(r[3]) : "r"(addr));
}
__device__ __forceinline__ void mma16816(float* d, const uint32_t* a,
                                         uint32_t b0, uint32_t b1) {
    asm volatile(
        "mma.sync.aligned.m16n8k16.row.col.f32.bf16.bf16.f32 "
        "{%0,%1,%2,%3}, {%4,%5,%6,%7}, {%8,%9}, {%0,%1,%2,%3};"
        : "+f"(d[0]), "+f"(d[1]), "+f"(d[2]), "+f"(d[3])
        : "r"(a[0]), "r"(a[1]), "r"(a[2]), "r"(a[3]), "r"(b0), "r"(b1));
}
// split fp32x4 -> packed bf16 hi pair + lo pair
__device__ __forceinline__ void split4(float4 v, uint2& h, uint2& l) {
    __nv_bfloat16 hx = __float2bfloat16(v.x), hy = __float2bfloat16(v.y),
                  hz = __float2bfloat16(v.z), hw = __float2bfloat16(v.w);
    float lx = v.x - __bfloat162float(hx), ly = v.y - __bfloat162float(hy),
          lz = v.z - __bfloat162float(hz), lw = v.w - __bfloat162float(hw);
    h.x = (uint32_t)__bfloat16_as_ushort(hx) | ((uint32_t)__bfloat16_as_ushort(hy) << 16);
    h.y = (uint32_t)__bfloat16_as_ushort(hz) | ((uint32_t)__bfloat16_as_ushort(hw) << 16);
    __nv_bfloat16 kx = __float2bfloat16(lx), ky = __float2bfloat16(ly),
                  kz = __float2bfloat16(lz), kw = __float2bfloat16(lw);
    l.x = (uint32_t)__bfloat16_as_ushort(kx) | ((uint32_t)__bfloat16_as_ushort(ky) << 16);
    l.y = (uint32_t)__bfloat16_as_ushort(kz) | ((uint32_t)__bfloat16_as_ushort(kw) << 16);
}
__device__ __forceinline__ void sts_split(uint32_t hi_a, uint32_t lo_a, float4 v) {
    uint2 h, l;
    split4(v, h, l);
    asm volatile("st.shared.v2.b32 [%0], {%1,%2};" :: "r"(hi_a), "r"(h.x), "r"(h.y) : "memory");
    asm volatile("st.shared.v2.b32 [%0], {%1,%2};" :: "r"(lo_a), "r"(l.x), "r"(l.y) : "memory");
}
__device__ __forceinline__ void sts_pair(uint32_t hi_a, uint32_t lo_a, uint2 h, uint2 l) {
    asm volatile("st.shared.v2.b32 [%0], {%1,%2};" :: "r"(hi_a), "r"(h.x), "r"(h.y) : "memory");
    asm volatile("st.shared.v2.b32 [%0], {%1,%2};" :: "r"(lo_a), "r"(l.x), "r"(l.y) : "memory");
}

// one K=32 chunk, warp tile 32x32; mmask bit per 16-row m-slice (warp-uniform)
__device__ __forceinline__ void compute_chunk(uint32_t sb, float acc[2][4][4],
                                              uint32_t aoff, uint32_t boff,
                                              int mmask) {
    if (!mmask) return;
#pragma unroll
    for (int ks = 0; ks < 2; ks++) {
        uint32_t ah[2][4], al[2][4];
#pragma unroll
        for (int mt = 0; mt < 2; mt++) {
            if (!(mmask & (1 << mt))) continue;
            uint32_t ao = aoff + mt * (16 * ROWB) + ks * 32;
            ldsm4(ah[mt], sb + O_AHI + ao);
            ldsm4(al[mt], sb + O_ALO + ao);
        }
#pragma unroll
        for (int ng = 0; ng < 2; ng++) {
            uint32_t bo = boff + ng * (16 * ROWB) + ks * 32;
            uint32_t bh[4], bl[4];
            ldsm4(bh, sb + O_BHI + bo);
            ldsm4(bl, sb + O_BLO + bo);
#pragma unroll
            for (int mt = 0; mt < 2; mt++)
                if (mmask & (1 << mt))
#pragma unroll
                    for (int t = 0; t < 2; t++)
                        mma16816(acc[mt][ng * 2 + t], ah[mt], bh[t], bh[2 + t]);
#pragma unroll
            for (int mt = 0; mt < 2; mt++)
                if (mmask & (1 << mt))
#pragma unroll
                    for (int t = 0; t < 2; t++)
                        mma16816(acc[mt][ng * 2 + t], ah[mt], bl[t], bl[2 + t]);
#pragma unroll
            for (int mt = 0; mt < 2; mt++)
                if (mmask & (1 << mt))
#pragma unroll
                    for (int t = 0; t < 2; t++)
                        mma16816(acc[mt][ng * 2 + t], al[mt], bh[t], bh[2 + t]);
        }
    }
}

// ---------------- router (fp32 exact: feeds top-k) -------------------------
__global__ void router_kernel(const float* __restrict__ x,
                              const float* __restrict__ gw,
                              float* __restrict__ logits_out)
{
    int t = blockIdx.x;
    int e = threadIdx.x;
    __shared__ float sl[NE];
    const float4* xr = (const float4*)(x + (size_t)t * HID);
    const float4* gr = (const float4*)(gw + (size_t)e * HID);
    float acc = 0.f;
#pragma unroll 4
    for (int k = 0; k < HID / 4; k++) {
        float4 a = xr[k], b = gr[k];
        acc += a.x * b.x + a.y * b.y + a.z * b.z + a.w * b.w;
    }
    sl[e] = acc;
    if (logits_out) logits_out[t * NE + e] = acc;
    __syncthreads();
    if (e == 0) {
        float tmp[NE];
        for (int i = 0; i < NE; i++) tmp[i] = sl[i];
        int sid[TOPK]; float lv[TOPK];
        for (int kk = 0; kk < TOPK; kk++) {
            int bi = 0; float bv = -3.4e38f;
            for (int i = 0; i < NE; i++)
                if (tmp[i] > bv) { bv = tmp[i]; bi = i; }
            sid[kk] = bi; lv[kk] = bv; tmp[bi] = -3.4e38f;
        }
        float m = lv[0], w[TOPK], s = 0.f;
        for (int kk = 0; kk < TOPK; kk++) { w[kk] = expf(lv[kk] - m); s += w[kk]; }
        float inv = 1.f / s;
        for (int kk = 0; kk < TOPK; kk++) {
            g_sel[t * TOPK + kk] = sid[kk];
            g_rw[t * TOPK + kk] = w[kk] * inv;
        }
    }
}

__global__ void zero_counts_kernel() { if (threadIdx.x < NE) g_counts[threadIdx.x] = 0; }

__global__ void dispatch_kernel()
{
    int a = blockIdx.x * blockDim.x + threadIdx.x;
    if (a >= TOK * TOPK) return;
    int e = g_sel[a];
    int s = atomicAdd(&g_counts[e], 1);
    if (s < CAP) {
        g_toklist[e * CAP + s] = a >> 3;
        g_slotw[e * CAP + s] = g_rw[a];
    }
}

__global__ void zero_out_kernel(float* __restrict__ out)
{
    int i = blockIdx.x * blockDim.x + threadIdx.x;
    if (i < TOK * HID / 4) ((float4*)out)[i] = make_float4(0, 0, 0, 0);
}

// ---------------- pre-split x into bf16 hi/lo -------------------------------
__global__ void asplit_kernel(const float* __restrict__ x)
{
    int i = blockIdx.x * blockDim.x + threadIdx.x;   // float4 index
    if (i >= TOK * HID / 4) return;
    float4 v = ((const float4*)x)[i];
    uint2 h, l;
    split4(v, h, l);
    ((uint2*)g_xhi)[i] = h;
    ((uint2*)g_xlo)[i] = l;
}

// ---------------- GEMM1: 128 tok x (64 g | 64 u), fused SwiGLU --------------
// 512 threads, 16 warps as 4m x 4n, warp tile 32x32
__global__ __launch_bounds__(512, 1) void gemm1_kernel(const float* __restrict__ w1,
                                                       const float* __restrict__ w3)
{
    int e = blockIdx.x, it = blockIdx.y, mtile = blockIdx.z;
    int cnt = min(g_counts[e], CAP);
    int m0 = mtile * 128;
    if (m0 >= cnt) return;
    int i0 = it * 64;

    extern __shared__ char smraw[];
    uint32_t sb0 = smem_u32(smraw);

    int tid = threadIdx.x, lane = tid & 31, wid = tid >> 5;
    int mr = (wid & 3) * 32, nc = (wid >> 2) * 32;
    int mmask = ((m0 + mr < cnt) ? 1 : 0) | ((m0 + mr + 16 < cnt) ? 2 : 0);

    int r = tid >> 3, c4 = tid & 7;          // 64 fill rows per pass, 2 passes
    long aoffg[2];
    const float* bpt[2];
    uint32_t sA[2], sB[2];
    bool aval[2];
#pragma unroll
    for (int p = 0; p < 2; p++) {
        int rp = r + 64 * p;
        int grw = m0 + rp;
        aval[p] = (m0 + (rp & ~15)) < cnt;
        aoffg[p] = (grw < cnt) ? (long)g_toklist[e * CAP + grw] * HID + c4 * 4 : -1;
        sA[p] = (uint32_t)(rp * ROWB + c4 * 8);
        // B rows: 0-63 w1[i0..], 64-127 w3[i0..]
        bpt[p] = (p == 0) ? w1 + ((size_t)e * NI + i0 + rp) * HID + c4 * 4
                          : w3 + ((size_t)e * NI + i0 + rp - 64) * HID + c4 * 4;
        sB[p] = (uint32_t)(rp * ROWB + c4 * 8);
    }

    uint32_t rowpart = (lane & 7) + ((lane >> 3) & 1) * 8;
    uint32_t colp = (lane >> 4) & 1;
    uint32_t aoff = (uint32_t)((mr + rowpart) * ROWB + colp * 16);
    uint32_t boff = (uint32_t)((nc + rowpart) * ROWB + colp * 16);

    float acc[2][4][4];
#pragma unroll
    for (int mt = 0; mt < 2; mt++)
#pragma unroll
        for (int n = 0; n < 4; n++)
#pragma unroll
            for (int q = 0; q < 4; q++) acc[mt][n][q] = 0.f;

    uint2 vah[2], val[2];
    float4 vb[2];
#pragma unroll
    for (int p = 0; p < 2; p++) {
        vah[p] = (aoffg[p] >= 0) ? *(const uint2*)(g_xhi + aoffg[p]) : make_uint2(0, 0);
        val[p] = (aoffg[p] >= 0) ? *(const uint2*)(g_xlo + aoffg[p]) : make_uint2(0, 0);
        vb[p] = __ldg((const float4*)bpt[p]);
    }
#pragma unroll
    for (int p = 0; p < 2; p++) {
        if (aval[p]) sts_pair(sb0 + O_AHI + sA[p], sb0 + O_ALO + sA[p], vah[p], val[p]);
        sts_split(sb0 + O_BHI + sB[p], sb0 + O_BLO + sB[p], vb[p]);
    }
    __syncthreads();

    const int NCH = HID / 32;
    for (int ch = 0; ch < NCH; ch++) {
        uint32_t cur = sb0 + (uint32_t)(ch & 1) * STAGE;
        bool more = (ch + 1 < NCH);
        if (more) {
            int off = (ch + 1) * 32;
#pragma unroll
            for (int p = 0; p < 2; p++) {
                vah[p] = (aoffg[p] >= 0) ? *(const uint2*)(g_xhi + aoffg[p] + off) : make_uint2(0, 0);
                val[p] = (aoffg[p] >= 0) ? *(const uint2*)(g_xlo + aoffg[p] + off) : make_uint2(0, 0);
                vb[p] = __ldg((const float4*)(bpt[p] + off));
            }
        }
        compute_chunk(cur, acc, aoff, boff, mmask);
        if (more) {
            uint32_t nxt = sb0 + (uint32_t)((ch + 1) & 1) * STAGE;
#pragma unroll
            for (int p = 0; p < 2; p++) {
                if (aval[p]) sts_pair(nxt + O_AHI + sA[p], nxt + O_ALO + sA[p], vah[p], val[p]);
                sts_split(nxt + O_BHI + sB[p], nxt + O_BLO + sB[p], vb[p]);
            }
        }
        __syncthreads();
    }

    // epilogue: stage 128x128 fp32 (stride 132), pair g/u, fused SwiGLU,
    // store h as split bf16 hi/lo
    float* stag = (float*)smraw;
    {
        int rbase = mr + (lane >> 2);
        int cb = nc + (lane & 3) * 2;
#pragma unroll
        for (int mt = 0; mt < 2; mt++)
#pragma unroll
            for (int n = 0; n < 4; n++) {
                int lr = rbase + mt * 16;
                int c = cb + n * 8;
                stag[lr * 132 + c]           = acc[mt][n][0];
                stag[lr * 132 + c + 1]       = acc[mt][n][1];
                stag[(lr + 8) * 132 + c]     = acc[mt][n][2];
                stag[(lr + 8) * 132 + c + 1] = acc[mt][n][3];
            }
    }
    __syncthreads();
    {
        int lr = tid >> 2, q = tid & 3;          // 128 rows, 4 threads/row
        int grow = m0 + lr;
        if (grow < cnt) {
            size_t base = ((size_t)e * CAP + grow) * NI + i0;
#pragma unroll
            for (int j = 0; j < 4; j++) {
                int c = q * 16 + j * 4;
                float4 g4 = *(float4*)&stag[lr * 132 + c];
                float4 u4 = *(float4*)&stag[lr * 132 + 64 + c];
                float4 o;
                o.x = g4.x / (1.f + expf(-g4.x)) * u4.x;
                o.y = g4.y / (1.f + expf(-g4.y)) * u4.y;
                o.z = g4.z / (1.f + expf(-g4.z)) * u4.z;
                o.w = g4.w / (1.f + expf(-g4.w)) * u4.w;
                uint2 h, l;
                split4(o, h, l);
                *(uint2*)(g_hhi + base + c) = h;
                *(uint2*)(g_hlo + base + c) = l;
            }
        }
    }
}

// ---------------- GEMM2: 128 tok x 128 h-cols, fused weighted combine -------
__global__ __launch_bounds__(512, 1) void gemm2_kernel(const float* __restrict__ w2,
                                                       float* __restrict__ out)
{
    int e = blockIdx.x, ht = blockIdx.y, mtile = blockIdx.z;
    int cnt = min(g_counts[e], CAP);
    int m0 = mtile * 128;
    if (m0 >= cnt) return;
    int h0 = ht * 128;

    extern __shared__ char smraw[];
    uint32_t sb0 = smem_u32(smraw);

    int tid = threadIdx.x, lane = tid & 31, wid = tid >> 5;
    int mr = (wid & 3) * 32, nc = (wid >> 2) * 32;
    int mmask = ((m0 + mr < cnt) ? 1 : 0) | ((m0 + mr + 16 < cnt) ? 2 : 0);

    int r = tid >> 3, c4 = tid & 7;
    long aoffg[2];
    const float* bpt[2];
    uint32_t sA[2], sB[2];
    bool aval[2];
#pragma unroll
    for (int p = 0; p < 2; p++) {
        int rp = r + 64 * p;
        int grw = m0 + rp;
        aval[p] = (m0 + (rp & ~15)) < cnt;
        aoffg[p] = (grw < cnt) ? (long)((size_t)e * CAP + grw) * NI + c4 * 4 : -1;
        sA[p] = (uint32_t)(rp * ROWB + c4 * 8);
        bpt[p] = w2 + ((size_t)e * HID + h0 + rp) * NI + c4 * 4;
        sB[p] = (uint32_t)(rp * ROWB + c4 * 8);
    }

    uint32_t rowpart = (lane & 7) + ((lane >> 3) & 1) * 8;
    uint32_t colp = (lane >> 4) & 1;
    uint32_t aoff = (uint32_t)((mr + rowpart) * ROWB + colp * 16);
    uint32_t boff = (uint32_t)((nc + rowpart) * ROWB + colp * 16);

    float acc[2][4][4];
#pragma unroll
    for (int mt = 0; mt < 2; mt++)
#pragma unroll
        for (int n = 0; n < 4; n++)
#pragma unroll
            for (int q = 0; q < 4; q++) acc[mt][n][q] = 0.f;

    uint2 vah[2], val[2];
    float4 vb[2];
#pragma unroll
    for (int p = 0; p < 2; p++) {
        vah[p] = (aoffg[p] >= 0) ? *(const uint2*)(g_hhi + aoffg[p]) : make_uint2(0, 0);
        val[p] = (aoffg[p] >= 0) ? *(const uint2*)(g_hlo + aoffg[p]) : make_uint2(0, 0);
        vb[p] = __ldg((const float4*)bpt[p]);
    }
#pragma unroll
    for (int p = 0; p < 2; p++) {
        if (aval[p]) sts_pair(sb0 + O_AHI + sA[p], sb0 + O_ALO + sA[p], vah[p], val[p]);
        sts_split(sb0 + O_BHI + sB[p], sb0 + O_BLO + sB[p], vb[p]);
    }
    __syncthreads();

    const int NCH = NI / 32;
    for (int ch = 0; ch < NCH; ch++) {
        uint32_t cur = sb0 + (uint32_t)(ch & 1) * STAGE;
        bool more = (ch + 1 < NCH);
        if (more) {
            int off = (ch + 1) * 32;
#pragma unroll
            for (int p = 0; p < 2; p++) {
                vah[p] = (aoffg[p] >= 0) ? *(const uint2*)(g_hhi + aoffg[p] + off) : make_uint2(0, 0);
                val[p] = (aoffg[p] >= 0) ? *(const uint2*)(g_hlo + aoffg[p] + off) : make_uint2(0, 0);
                vb[p] = __ldg((const float4*)(bpt[p] + off));
            }
        }
        compute_chunk(cur, acc, aoff, boff, mmask);
        if (more) {
            uint32_t nxt = sb0 + (uint32_t)((ch + 1) & 1) * STAGE;
#pragma unroll
            for (int p = 0; p < 2; p++) {
                if (aval[p]) sts_pair(nxt + O_AHI + sA[p], nxt + O_ALO + sA[p], vah[p], val[p]);
                sts_split(nxt + O_BHI + sB[p], nxt + O_BLO + sB[p], vb[p]);
            }
        }
        __syncthreads();
    }

    // fused combine: out[token] += w * y
    int rb = mr + (lane >> 2);
    int cb = h0 + nc + (lane & 3) * 2;
#pragma unroll
    for (int mt = 0; mt < 2; mt++)
#pragma unroll
        for (int half = 0; half < 2; half++) {
            int grow = m0 + rb + mt * 16 + half * 8;
            if (grow < cnt) {
                int tok = g_toklist[e * CAP + grow];
                float w = g_slotw[e * CAP + grow];
                float* dst = out + (size_t)tok * HID;
#pragma unroll
                for (int n = 0; n < 4; n++) {
                    int c = cb + n * 8;
                    atomicAdd(dst + c,     w * acc[mt][n][half * 2 + 0]);
                    atomicAdd(dst + c + 1, w * acc[mt][n][half * 2 + 1]);
                }
            }
        }
}

// ---------------- launch ---------------------------------------------------
extern "C" void kernel_launch(void* const* d_in, const int* in_sizes, int n_in,
                              void* d_out, int out_size)
{
    const float* x  = (const float*)d_in[0];
    const float* gw = (const float*)d_in[1];
    const float* w1 = (const float*)d_in[2];
    const float* w2 = (const float*)d_in[3];
    const float* w3 = (const float*)d_in[4];
    float* out = (float*)d_out;
    float* logits = (out_size >= TOK * HID + TOK * NE) ? out + (size_t)TOK * HID : nullptr;

    cudaFuncSetAttribute(gemm1_kernel, cudaFuncAttributeMaxDynamicSharedMemorySize, SMEM_BYTES);
    cudaFuncSetAttribute(gemm2_kernel, cudaFuncAttributeMaxDynamicSharedMemorySize, SMEM_BYTES);

    zero_counts_kernel<<<1, 64>>>();
    router_kernel<<<TOK, 64>>>(x, gw, logits);
    dispatch_kernel<<<(TOK * TOPK + 255) / 256, 256>>>();
    asplit_kernel<<<(TOK * HID / 4 + 255) / 256, 256>>>(x);
    zero_out_kernel<<<(TOK * HID / 4 + 255) / 256, 256>>>(out);

    dim3 g1(NE, NI / 64, CAP / 128);
    gemm1_kernel<<<g1, 512, SMEM_BYTES>>>(w1, w3);

    dim3 g2(NE, HID / 128, CAP / 128);
    gemm2_kernel<<<g2, 512, SMEM_BYTES>>>(w2, out);
}

// round 17
// speedup vs baseline: 1.3931x; 1.3931x over previous
#include <cuda_runtime.h>
#include <cuda_bf16.h>
#include <cstdint>

#define TOK 512
#define HID 2048
#define NE  64
#define NI  768
#define TOPK 8
#define CAP 256

#define ROWB   80u                 // smem row stride bytes (32 bf16 + 16B pad)
#define AT_B   (64u * ROWB)        // 5120  : A tile (64 rows)
#define BT_B   (128u * ROWB)       // 10240 : B tile (128 rows)
#define O_AHI  0u
#define O_ALO  AT_B
#define O_BHI  (2u * AT_B)
#define O_BLO  (2u * AT_B + BT_B)
#define STAGE  (2u * AT_B + 2u * BT_B)   // 30720 B
#define SMEM_BYTES (2 * STAGE)           // 61440 B

// ---------------- scratch (static device allocations) ----------------------
__device__ int   g_counts[NE];
__device__ int   g_sel[TOK * TOPK];
__device__ float g_rw[TOK * TOPK];
__device__ int   g_toklist[NE * CAP];
__device__ float g_slotw[NE * CAP];
__device__ unsigned short g_xhi[(size_t)TOK * HID];
__device__ unsigned short g_xlo[(size_t)TOK * HID];
__device__ unsigned short g_hhi[(size_t)NE * CAP * NI];
__device__ unsigned short g_hlo[(size_t)NE * CAP * NI];

// ---------------- helpers ---------------------------------------------------
__device__ __forceinline__ uint32_t smem_u32(const void* p) {
    uint32_t a;
    asm("{ .reg .u64 t; cvta.to.shared.u64 t, %1; cvt.u32.u64 %0, t; }"
        : "=r"(a) : "l"(p));
    return a;
}
__device__ __forceinline__ void ldsm4(uint32_t* r, uint32_t addr) {
    asm volatile("ldmatrix.sync.aligned.m8n8.x4.shared.b16 {%0,%1,%2,%3}, [%4];"
                 : "=r"(r[0]), "=r"(r[1]), "=r"(r[2]), "=r"(r[3]) : "r"(addr));
}
__device__ __forceinline__ void mma16816(float* d, const uint32_t* a,
                                         uint32_t b0, uint32_t b1) {
    asm volatile(
        "mma.sync.aligned.m16n8k16.row.col.f32.bf16.bf16.f32 "
        "{%0,%1,%2,%3}, {%4,%5,%6,%7}, {%8,%9}, {%0,%1,%2,%3};"
        : "+f"(d[0]), "+f"(d[1]), "+f"(d[2]), "+f"(d[3])
        : "r"(a[0]), "r"(a[1]), "r"(a[2]), "r"(a[3]), "r"(b0), "r"(b1));
}
#define CP_ASYNC16(smem, gptr, sz) \
    asm volatile("cp.async.ca.shared.global [%0], [%1], 16, %2;" \
                 :: "r"(smem), "l"(gptr), "r"(sz) : "memory")
#define CP_COMMIT() asm volatile("cp.async.commit_group;" ::: "memory")
#define CP_WAIT0()  asm volatile("cp.async.wait_group 0;" ::: "memory")

// split fp32x4 -> packed bf16 hi pair + lo pair
__device__ __forceinline__ void split4(float4 v, uint2& h, uint2& l) {
    __nv_bfloat16 hx = __float2bfloat16(v.x), hy = __float2bfloat16(v.y),
                  hz = __float2bfloat16(v.z), hw = __float2bfloat16(v.w);
    float lx = v.x - __bfloat162float(hx), ly = v.y - __bfloat162float(hy),
          lz = v.z - __bfloat162float(hz), lw = v.w - __bfloat162float(hw);
    h.x = (uint32_t)__bfloat16_as_ushort(hx) | ((uint32_t)__bfloat16_as_ushort(hy) << 16);
    h.y = (uint32_t)__bfloat16_as_ushort(hz) | ((uint32_t)__bfloat16_as_ushort(hw) << 16);
    __nv_bfloat16 kx = __float2bfloat16(lx), ky = __float2bfloat16(ly),
                  kz = __float2bfloat16(lz), kw = __float2bfloat16(lw);
    l.x = (uint32_t)__bfloat16_as_ushort(kx) | ((uint32_t)__bfloat16_as_ushort(ky) << 16);
    l.y = (uint32_t)__bfloat16_as_ushort(kz) | ((uint32_t)__bfloat16_as_ushort(kw) << 16);
}
__device__ __forceinline__ void sts_split(uint32_t hi_a, uint32_t lo_a, float4 v) {
    uint2 h, l;
    split4(v, h, l);
    asm volatile("st.shared.v2.b32 [%0], {%1,%2};" :: "r"(hi_a), "r"(h.x), "r"(h.y) : "memory");
    asm volatile("st.shared.v2.b32 [%0], {%1,%2};" :: "r"(lo_a), "r"(l.x), "r"(l.y) : "memory");
}
// split fp32 pair -> packed bf16 hi u32 + lo u32
__device__ __forceinline__ void split2(float a, float b, uint32_t& h, uint32_t& l) {
    __nv_bfloat16 ha = __float2bfloat16(a), hb = __float2bfloat16(b);
    float la = a - __bfloat162float(ha), lb = b - __bfloat162float(hb);
    h = (uint32_t)__bfloat16_as_ushort(ha) | ((uint32_t)__bfloat16_as_ushort(hb) << 16);
    __nv_bfloat16 ka = __float2bfloat16(la), kb = __float2bfloat16(lb);
    l = (uint32_t)__bfloat16_as_ushort(ka) | ((uint32_t)__bfloat16_as_ushort(kb) << 16);
}

// one K=32 chunk, warp tile 32x32; mmask bit per 16-row m-slice (warp-uniform)
__device__ __forceinline__ void compute_chunk(uint32_t sb, float acc[2][4][4],
                                              uint32_t aoff, uint32_t boff,
                                              int mmask) {
    if (!mmask) return;
#pragma unroll
    for (int ks = 0; ks < 2; ks++) {
        uint32_t ah[2][4], al[2][4];
#pragma unroll
        for (int mt = 0; mt < 2; mt++) {
            if (!(mmask & (1 << mt))) continue;
            uint32_t ao = aoff + mt * (16 * ROWB) + ks * 32;
            ldsm4(ah[mt], sb + O_AHI + ao);
            ldsm4(al[mt], sb + O_ALO + ao);
        }
#pragma unroll
        for (int ng = 0; ng < 2; ng++) {
            uint32_t bo = boff + ng * (16 * ROWB) + ks * 32;
            uint32_t bh[4], bl[4];
            ldsm4(bh, sb + O_BHI + bo);
            ldsm4(bl, sb + O_BLO + bo);
#pragma unroll
            for (int mt = 0; mt < 2; mt++)
                if (mmask & (1 << mt))
#pragma unroll
                    for (int t = 0; t < 2; t++)
                        mma16816(acc[mt][ng * 2 + t], ah[mt], bh[t], bh[2 + t]);
#pragma unroll
            for (int mt = 0; mt < 2; mt++)
                if (mmask & (1 << mt))
#pragma unroll
                    for (int t = 0; t < 2; t++)
                        mma16816(acc[mt][ng * 2 + t], ah[mt], bl[t], bl[2 + t]);
#pragma unroll
            for (int mt = 0; mt < 2; mt++)
                if (mmask & (1 << mt))
#pragma unroll
                    for (int t = 0; t < 2; t++)
                        mma16816(acc[mt][ng * 2 + t], al[mt], bh[t], bh[2 + t]);
        }
    }
}

// ---------------- router (fp32 exact: feeds top-k) -------------------------
__global__ void router_kernel(const float* __restrict__ x,
                              const float* __restrict__ gw,
                              float* __restrict__ logits_out)
{
    int t = blockIdx.x;
    int e = threadIdx.x;
    __shared__ float sl[NE];
    const float4* xr = (const float4*)(x + (size_t)t * HID);
    const float4* gr = (const float4*)(gw + (size_t)e * HID);
    float acc = 0.f;
#pragma unroll 4
    for (int k = 0; k < HID / 4; k++) {
        float4 a = xr[k], b = gr[k];
        acc += a.x * b.x + a.y * b.y + a.z * b.z + a.w * b.w;
    }
    sl[e] = acc;
    if (logits_out) logits_out[t * NE + e] = acc;
    __syncthreads();
    if (e == 0) {
        float tmp[NE];
        for (int i = 0; i < NE; i++) tmp[i] = sl[i];
        int sid[TOPK]; float lv[TOPK];
        for (int kk = 0; kk < TOPK; kk++) {
            int bi = 0; float bv = -3.4e38f;
            for (int i = 0; i < NE; i++)
                if (tmp[i] > bv) { bv = tmp[i]; bi = i; }
            sid[kk] = bi; lv[kk] = bv; tmp[bi] = -3.4e38f;
        }
        float m = lv[0], w[TOPK], s = 0.f;
        for (int kk = 0; kk < TOPK; kk++) { w[kk] = expf(lv[kk] - m); s += w[kk]; }
        float inv = 1.f / s;
        for (int kk = 0; kk < TOPK; kk++) {
            g_sel[t * TOPK + kk] = sid[kk];
            g_rw[t * TOPK + kk] = w[kk] * inv;
        }
    }
}

__global__ void zero_counts_kernel() { if (threadIdx.x < NE) g_counts[threadIdx.x] = 0; }

__global__ void dispatch_kernel()
{
    int a = blockIdx.x * blockDim.x + threadIdx.x;
    if (a >= TOK * TOPK) return;
    int e = g_sel[a];
    int s = atomicAdd(&g_counts[e], 1);
    if (s < CAP) {
        g_toklist[e * CAP + s] = a >> 3;
        g_slotw[e * CAP + s] = g_rw[a];
    }
}

__global__ void zero_out_kernel(float* __restrict__ out)
{
    int i = blockIdx.x * blockDim.x + threadIdx.x;
    if (i < TOK * HID / 4) ((float4*)out)[i] = make_float4(0, 0, 0, 0);
}

// ---------------- pre-split x into bf16 hi/lo -------------------------------
__global__ void asplit_kernel(const float* __restrict__ x)
{
    int i = blockIdx.x * blockDim.x + threadIdx.x;   // float4 index
    if (i >= TOK * HID / 4) return;
    float4 v = ((const float4*)x)[i];
    uint2 h, l;
    split4(v, h, l);
    ((uint2*)g_xhi)[i] = h;
    ((uint2*)g_xlo)[i] = l;
}

// ---------------- GEMM1: 64 tok x 64 i-cols (w1+w3 interleaved B) -----------
// B tile rows: 16-row groups alternate w1/w3 over the same i-range, so each
// warp's acc holds aligned g (ng=0) and u (ng=1) fragments -> in-register SwiGLU.
__global__ __launch_bounds__(256, 2) void gemm1_kernel(const float* __restrict__ w1,
                                                       const float* __restrict__ w3)
{
    int e = blockIdx.x, it = blockIdx.y, mtile = blockIdx.z;
    int cnt = min(g_counts[e], CAP);
    int m0 = mtile * 64;
    if (m0 >= cnt) return;
    int i0 = it * 64;

    extern __shared__ char smraw[];
    uint32_t sb0 = smem_u32(smraw);

    int tid = threadIdx.x, lane = tid & 31, wid = tid >> 5;
    int mr = (wid & 1) * 32, wc = wid >> 1, nc = wc * 32;
    int mmask = ((m0 + mr < cnt) ? 1 : 0) | ((m0 + mr + 16 < cnt) ? 2 : 0);

    // A via cp.async: 1 row per thread (64 rows), 16B hi + 16B lo
    int arow = tid >> 2, ac = tid & 3;
    int agrw = m0 + arow;
    uint32_t avalid = (agrw < cnt) ? 16u : 0u;
    const char* aghi;
    const char* aglo;
    {
        long toff = (agrw < cnt) ? (long)g_toklist[e * CAP + agrw] * HID : 0;
        aghi = (const char*)(g_xhi + toff) + ac * 16;
        aglo = (const char*)(g_xlo + toff) + ac * 16;
    }
    uint32_t sAa = (uint32_t)(arow * ROWB + ac * 16);

    // B fill: interleaved w1/w3 16-row groups
    int r = tid >> 3, c4 = tid & 7;
    const float* bpt[4];
    uint32_t sB[4];
#pragma unroll
    for (int p = 0; p < 4; p++) {
        int j = r + 32 * p;
        int grp = j >> 4, win = j & 15;
        int irow = i0 + (grp >> 1) * 16 + win;
        const float* W = (grp & 1) ? w3 : w1;
        bpt[p] = W + ((size_t)e * NI + irow) * HID + c4 * 4;
        sB[p] = (uint32_t)(j * ROWB + c4 * 8);
    }

    uint32_t rowpart = (lane & 7) + ((lane >> 3) & 1) * 8;
    uint32_t colp = (lane >> 4) & 1;
    uint32_t aoff = (uint32_t)((mr + rowpart) * ROWB + colp * 16);
    uint32_t boff = (uint32_t)((nc + rowpart) * ROWB + colp * 16);

    float acc[2][4][4];
#pragma unroll
    for (int mt = 0; mt < 2; mt++)
#pragma unroll
        for (int n = 0; n < 4; n++)
#pragma unroll
            for (int q = 0; q < 4; q++) acc[mt][n][q] = 0.f;

    // prologue: fill stage 0
    CP_ASYNC16(sb0 + O_AHI + sAa, aghi, avalid);
    CP_ASYNC16(sb0 + O_ALO + sAa, aglo, avalid);
    CP_COMMIT();
    float4 vb[4];
#pragma unroll
    for (int p = 0; p < 4; p++) vb[p] = __ldg((const float4*)bpt[p]);
#pragma unroll
    for (int p = 0; p < 4; p++) sts_split(sb0 + O_BHI + sB[p], sb0 + O_BLO + sB[p], vb[p]);
    CP_WAIT0();
    __syncthreads();

    const int NCH = HID / 32;
    for (int ch = 0; ch < NCH; ch++) {
        uint32_t cur = sb0 + (uint32_t)(ch & 1) * STAGE;
        uint32_t nxt = sb0 + (uint32_t)((ch + 1) & 1) * STAGE;
        bool more = (ch + 1 < NCH);
        if (more) {
            int koffb = (ch + 1) * 64;     // bytes: 32 bf16
            CP_ASYNC16(nxt + O_AHI + sAa, aghi + koffb, avalid);
            CP_ASYNC16(nxt + O_ALO + sAa, aglo + koffb, avalid);
            CP_COMMIT();
            int offe = (ch + 1) * 32;      // fp32 elements
#pragma unroll
            for (int p = 0; p < 4; p++) vb[p] = __ldg((const float4*)(bpt[p] + offe));
        }
        compute_chunk(cur, acc, aoff, boff, mmask);
        if (more) {
#pragma unroll
            for (int p = 0; p < 4; p++)
                sts_split(nxt + O_BHI + sB[p], nxt + O_BLO + sB[p], vb[p]);
        }
        CP_WAIT0();
        __syncthreads();
    }

    // in-register SwiGLU epilogue: g = acc[.][t], u = acc[.][2+t] (same cols)
    int lq = lane >> 2, lp = lane & 3;
#pragma unroll
    for (int mt = 0; mt < 2; mt++)
#pragma unroll
        for (int half = 0; half < 2; half++) {
            int row = m0 + mr + mt * 16 + lq + half * 8;
            if (row < cnt) {
                size_t base = ((size_t)e * CAP + row) * NI;
#pragma unroll
                for (int t = 0; t < 2; t++) {
                    int col = i0 + wc * 16 + t * 8 + lp * 2;
                    float g0 = acc[mt][t][half * 2 + 0];
                    float g1 = acc[mt][t][half * 2 + 1];
                    float u0 = acc[mt][2 + t][half * 2 + 0];
                    float u1 = acc[mt][2 + t][half * 2 + 1];
                    float o0 = g0 / (1.f + expf(-g0)) * u0;
                    float o1 = g1 / (1.f + expf(-g1)) * u1;
                    uint32_t hp, lpk;
                    split2(o0, o1, hp, lpk);
                    *(uint32_t*)(g_hhi + base + col) = hp;
                    *(uint32_t*)(g_hlo + base + col) = lpk;
                }
            }
        }
}

// ---------------- GEMM2: 64 tok x 128 h-cols, fused weighted combine --------
__global__ __launch_bounds__(256, 2) void gemm2_kernel(const float* __restrict__ w2,
                                                       float* __restrict__ out)
{
    int e = blockIdx.x, ht = blockIdx.y, mtile = blockIdx.z;
    int cnt = min(g_counts[e], CAP);
    int m0 = mtile * 64;
    if (m0 >= cnt) return;
    int h0 = ht * 128;

    extern __shared__ char smraw[];
    uint32_t sb0 = smem_u32(smraw);

    int tid = threadIdx.x, lane = tid & 31, wid = tid >> 5;
    int mr = (wid & 1) * 32, nc = (wid >> 1) * 32;
    int mmask = ((m0 + mr < cnt) ? 1 : 0) | ((m0 + mr + 16 < cnt) ? 2 : 0);

    // A via cp.async from pre-split h
    int arow = tid >> 2, ac = tid & 3;
    int agrw = m0 + arow;
    uint32_t avalid = (agrw < cnt) ? 16u : 0u;
    const char* aghi;
    const char* aglo;
    {
        long toff = (agrw < cnt) ? (long)((size_t)e * CAP + agrw) * NI : 0;
        aghi = (const char*)(g_hhi + toff) + ac * 16;
        aglo = (const char*)(g_hlo + toff) + ac * 16;
    }
    uint32_t sAa = (uint32_t)(arow * ROWB + ac * 16);

    int r = tid >> 3, c4 = tid & 7;
    const float* bpt[4];
    uint32_t sB[4];
#pragma unroll
    for (int p = 0; p < 4; p++) {
        int rp = r + 32 * p;
        bpt[p] = w2 + ((size_t)e * HID + h0 + rp) * NI + c4 * 4;
        sB[p] = (uint32_t)(rp * ROWB + c4 * 8);
    }

    uint32_t rowpart = (lane & 7) + ((lane >> 3) & 1) * 8;
    uint32_t colp = (lane >> 4) & 1;
    uint32_t aoff = (uint32_t)((mr + rowpart) * ROWB + colp * 16);
    uint32_t boff = (uint32_t)((nc + rowpart) * ROWB + colp * 16);

    float acc[2][4][4];
#pragma unroll
    for (int mt = 0; mt < 2; mt++)
#pragma unroll
        for (int n = 0; n < 4; n++)
#pragma unroll
            for (int q = 0; q < 4; q++) acc[mt][n][q] = 0.f;

    CP_ASYNC16(sb0 + O_AHI + sAa, aghi, avalid);
    CP_ASYNC16(sb0 + O_ALO + sAa, aglo, avalid);
    CP_COMMIT();
    float4 vb[4];
#pragma unroll
    for (int p = 0; p < 4; p++) vb[p] = __ldg((const float4*)bpt[p]);
#pragma unroll
    for (int p = 0; p < 4; p++) sts_split(sb0 + O_BHI + sB[p], sb0 + O_BLO + sB[p], vb[p]);
    CP_WAIT0();
    __syncthreads();

    const int NCH = NI / 32;
    for (int ch = 0; ch < NCH; ch++) {
        uint32_t cur = sb0 + (uint32_t)(ch & 1) * STAGE;
        uint32_t nxt = sb0 + (uint32_t)((ch + 1) & 1) * STAGE;
        bool more = (ch + 1 < NCH);
        if (more) {
            int koffb = (ch + 1) * 64;
            CP_ASYNC16(nxt + O_AHI + sAa, aghi + koffb, avalid);
            CP_ASYNC16(nxt + O_ALO + sAa, aglo + koffb, avalid);
            CP_COMMIT();
            int offe = (ch + 1) * 32;
#pragma unroll
            for (int p = 0; p < 4; p++) vb[p] = __ldg((const float4*)(bpt[p] + offe));
        }
        compute_chunk(cur, acc, aoff, boff, mmask);
        if (more) {
#pragma unroll
            for (int p = 0; p < 4; p++)
                sts_split(nxt + O_BHI + sB[p], nxt + O_BLO + sB[p], vb[p]);
        }
        CP_WAIT0();
        __syncthreads();
    }

    // fused combine: out[token] += w * y
    int rb = mr + (lane >> 2);
    int cb = h0 + nc + (lane & 3) * 2;
#pragma unroll
    for (int mt = 0; mt < 2; mt++)
#pragma unroll
        for (int half = 0; half < 2; half++) {
            int grow = m0 + rb + mt * 16 + half * 8;
            if (grow < cnt) {
                int tok = g_toklist[e * CAP + grow];
                float w = g_slotw[e * CAP + grow];
                float* dst = out + (size_t)tok * HID;
#pragma unroll
                for (int n = 0; n < 4; n++) {
                    int c = cb + n * 8;
                    atomicAdd(dst + c,     w * acc[mt][n][half * 2 + 0]);
                    atomicAdd(dst + c + 1, w * acc[mt][n][half * 2 + 1]);
                }
            }
        }
}

// ---------------- launch ---------------------------------------------------
extern "C" void kernel_launch(void* const* d_in, const int* in_sizes, int n_in,
                              void* d_out, int out_size)
{
    const float* x  = (const float*)d_in[0];
    const float* gw = (const float*)d_in[1];
    const float* w1 = (const float*)d_in[2];
    const float* w2 = (const float*)d_in[3];
    const float* w3 = (const float*)d_in[4];
    float* out = (float*)d_out;
    float* logits = (out_size >= TOK * HID + TOK * NE) ? out + (size_t)TOK * HID : nullptr;

    cudaFuncSetAttribute(gemm1_kernel, cudaFuncAttributeMaxDynamicSharedMemorySize, SMEM_BYTES);
    cudaFuncSetAttribute(gemm2_kernel, cudaFuncAttributeMaxDynamicSharedMemorySize, SMEM_BYTES);

    zero_counts_kernel<<<1, 64>>>();
    router_kernel<<<TOK, 64>>>(x, gw, logits);
    dispatch_kernel<<<(TOK * TOPK + 255) / 256, 256>>>();
    asplit_kernel<<<(TOK * HID / 4 + 255) / 256, 256>>>(x);
    zero_out_kernel<<<(TOK * HID / 4 + 255) / 256, 256>>>(out);

    dim3 g1(NE, NI / 64, CAP / 64);
    gemm1_kernel<<<g1, 256, SMEM_BYTES>>>(w1, w3);

    dim3 g2(NE, HID / 128, CAP / 64);
    gemm2_kernel<<<g2, 256, SMEM_BYTES>>>(w2, out);
}